// round 1
// baseline (speedup 1.0000x reference)
#include <cuda_runtime.h>

// ---------------- problem constants ----------------
#define Bn   32      // batch
#define Tn   8       // task vectors
#define Dd   768     // patch dim
#define DHh  3072    // hidden
#define Ff   512     // feat dim
#define MHh  128     // meta hidden
#define Pp   196     // patches per image
#define BP   (Bn*Pp) // 6272 total rows

// ---------------- device scratch (no cudaMalloc allowed) ----------------
__device__ float g_p   [(long)BP * Dd];        // patchified input     [6272,768]
__device__ float g_h   [(long)BP * Dd];        // base layer1 out      [6272,768]
__device__ float g_hb  [(long)BP * Dd];        // adapted layer1 out   [6272,768]
__device__ float g_h2  [(long)BP * DHh];       // layer2 out (reused)  [6272,3072]
__device__ float g_h2m [(long)Bn * DHh];       // pooled               [32,3072]
__device__ float g_base[(long)Bn * Ff];        // base features        [32,512]
__device__ float g_coef[(long)Bn * Tn];        // coefficients         [32,8]
__device__ float g_W1b [(long)Bn * Dd * Dd];   // composed W1          [32,768,768]
__device__ float g_W2b [(long)Bn * Dd * DHh];  // composed W2          [32,768,3072]
__device__ float g_W3b [(long)Bn * DHh * Ff];  // composed W3          [32,3072,512]
__device__ float g_b1b [(long)Bn * Dd];
__device__ float g_b2b [(long)Bn * DHh];
__device__ float g_b3b [(long)Bn * Ff];

// ---------------- patchify: x[B,3,224,224] -> p[B*196,768] ----------------
__global__ void patchify_kernel(const float* __restrict__ x, float* __restrict__ p) {
    long idx = (long)blockIdx.x * blockDim.x + threadIdx.x;
    if (idx >= (long)BP * Dd) return;
    int d     = (int)(idx % Dd);
    long rem  = idx / Dd;
    int patch = (int)(rem % Pp);
    int b     = (int)(rem / Pp);
    int pi = patch / 14, pj = patch % 14;
    int c = d >> 8;            // d / 256
    int r = (d >> 4) & 15;     // (d/16) % 16
    int s = d & 15;            // d % 16
    p[idx] = x[((long)(b * 3 + c) * 224 + pi * 16 + r) * 224 + pj * 16 + s];
}

// ---------------- generic batched tiled GEMM ----------------
// C[b] = act(A[b] (MxK, row-major) @ W[b] (KxN, row-major) + bias[b])
// 64x64 tile, BK=16, 256 threads, 4x4 register micro-tile.
// K % 16 == 0 and N % 64 == 0 guaranteed by problem shapes; only M has edge.
__global__ void gemm_kernel(const float* __restrict__ A, long aStride,
                            const float* __restrict__ W, long wStride,
                            const float* __restrict__ bias, long biasStride,
                            float* __restrict__ C, long cStride,
                            int M, int N, int K, int doRelu)
{
    int b = blockIdx.z;
    A    += (long)b * aStride;
    W    += (long)b * wStride;
    bias += (long)b * biasStride;
    C    += (long)b * cStride;

    __shared__ float As[16][64];
    __shared__ float Ws[16][64];

    int m0 = blockIdx.x * 64;
    int n0 = blockIdx.y * 64;
    int tid = threadIdx.x;       // 0..255
    int tx = tid & 15;           // col group
    int ty = tid >> 4;           // row group

    // load mappings
    int la_k = tid & 15;         // k index for A tile
    int la_m = tid >> 4;         // base row (16 rows per pass)
    int lw_n = tid & 63;         // n index for W tile
    int lw_k = tid >> 6;         // base k (4 per pass)

    float acc[4][4] = {};

    for (int k0 = 0; k0 < K; k0 += 16) {
        #pragma unroll
        for (int i = 0; i < 4; i++) {
            int m = m0 + la_m + i * 16;
            float v = 0.f;
            if (m < M) v = A[(long)m * K + k0 + la_k];
            As[la_k][la_m + i * 16] = v;
        }
        #pragma unroll
        for (int i = 0; i < 4; i++) {
            int kk = lw_k + i * 4;
            Ws[kk][lw_n] = W[(long)(k0 + kk) * N + n0 + lw_n];
        }
        __syncthreads();
        #pragma unroll
        for (int kk = 0; kk < 16; kk++) {
            float a[4], w[4];
            #pragma unroll
            for (int i = 0; i < 4; i++) a[i] = As[kk][ty * 4 + i];
            #pragma unroll
            for (int j = 0; j < 4; j++) w[j] = Ws[kk][tx * 4 + j];
            #pragma unroll
            for (int i = 0; i < 4; i++)
                #pragma unroll
                for (int j = 0; j < 4; j++)
                    acc[i][j] = fmaf(a[i], w[j], acc[i][j]);
        }
        __syncthreads();
    }

    #pragma unroll
    for (int i = 0; i < 4; i++) {
        int m = m0 + ty * 4 + i;
        if (m >= M) continue;
        #pragma unroll
        for (int j = 0; j < 4; j++) {
            int n = n0 + tx * 4 + j;
            float v = acc[i][j] + bias[n];
            if (doRelu) v = fmaxf(v, 0.f);
            C[(long)m * N + n] = v;
        }
    }
}

// ---------------- mean over the 196 patch rows per sample ----------------
__global__ void mean_kernel(const float* __restrict__ H2, float* __restrict__ out) {
    int idx = blockIdx.x * blockDim.x + threadIdx.x; // b*DHh + f
    if (idx >= Bn * DHh) return;
    int b = idx / DHh, f = idx % DHh;
    const float* col = H2 + (long)b * Pp * DHh + f;
    float s = 0.f;
    for (int i = 0; i < Pp; i++) s += col[(long)i * DHh];
    out[idx] = s * (1.f / (float)Pp);
}

// ---------------- small-M GEMM: out[b,n] = A[b,:] @ W_b[:,n] + bias_b[n] ----------------
// grid = (Bn, N/blockDim), one thread per output column
__global__ void rowgemm_kernel(const float* __restrict__ A,
                               const float* __restrict__ W, long wStride,
                               const float* __restrict__ bias, long biasStride,
                               float* __restrict__ C, int N, int K)
{
    int b = blockIdx.x;
    int n = blockIdx.y * blockDim.x + threadIdx.x;
    const float* a = A + (long)b * K;
    const float* w = W + (long)b * wStride;
    float acc = 0.f;
    for (int k = 0; k < K; k++) acc = fmaf(a[k], w[(long)k * N + n], acc);
    C[(long)b * N + n] = acc + bias[(long)b * biasStride + n];
}

// ---------------- MetaNet: coefs = relu(base@mW1+mb1)@mW2 + mb2 ----------------
__global__ void meta_kernel(const float* __restrict__ base,
                            const float* __restrict__ mW1, const float* __restrict__ mb1,
                            const float* __restrict__ mW2, const float* __restrict__ mb2,
                            float* __restrict__ coef)
{
    int b = blockIdx.x;
    __shared__ float br[Ff];
    __shared__ float hid[MHh];
    int t = threadIdx.x; // 128
    for (int i = t; i < Ff; i += MHh) br[i] = base[b * Ff + i];
    __syncthreads();
    float acc = mb1[t];
    for (int e = 0; e < Ff; e++) acc = fmaf(br[e], mW1[e * MHh + t], acc);
    hid[t] = fmaxf(acc, 0.f);
    __syncthreads();
    if (t < Tn) {
        float c = mb2[t];
        for (int j = 0; j < MHh; j++) c = fmaf(hid[j], mW2[j * Tn + t], c);
        coef[b * Tn + t] = c;
    }
}

// ---------------- compose: out[b*S+i] = W[i] + sum_t coef[b,t]*dW[t*S+i] ----------------
// Each thread owns one element i, loops over all 32 samples (dW read once).
__global__ void compose_kernel(const float* __restrict__ W, const float* __restrict__ dW,
                               const float* __restrict__ coef, float* __restrict__ out, long S)
{
    __shared__ float cs[Bn * Tn];
    if (threadIdx.x < Bn * Tn) cs[threadIdx.x] = coef[threadIdx.x];
    __syncthreads();
    long i = (long)blockIdx.x * blockDim.x + threadIdx.x;
    if (i >= S) return;
    float w = W[i];
    float d[Tn];
    #pragma unroll
    for (int t = 0; t < Tn; t++) d[t] = dW[(long)t * S + i];
    #pragma unroll 4
    for (int b = 0; b < Bn; b++) {
        float v = w;
        #pragma unroll
        for (int t = 0; t < Tn; t++) v = fmaf(cs[b * Tn + t], d[t], v);
        out[(long)b * S + i] = v;
    }
}

// ---------------- launch ----------------
extern "C" void kernel_launch(void* const* d_in, const int* in_sizes, int n_in,
                              void* d_out, int out_size)
{
    const float* x   = (const float*)d_in[0];
    const float* W1  = (const float*)d_in[1];
    const float* b1  = (const float*)d_in[2];
    const float* W2  = (const float*)d_in[3];
    const float* b2  = (const float*)d_in[4];
    const float* W3  = (const float*)d_in[5];
    const float* b3  = (const float*)d_in[6];
    const float* dW1 = (const float*)d_in[7];
    const float* db1 = (const float*)d_in[8];
    const float* dW2 = (const float*)d_in[9];
    const float* db2 = (const float*)d_in[10];
    const float* dW3 = (const float*)d_in[11];
    const float* db3 = (const float*)d_in[12];
    const float* mW1 = (const float*)d_in[13];
    const float* mb1 = (const float*)d_in[14];
    const float* mW2 = (const float*)d_in[15];
    const float* mb2 = (const float*)d_in[16];
    float* out = (float*)d_out;

    float *p, *h, *hb, *h2, *h2m, *base, *coef;
    float *W1b, *W2b, *W3b, *b1b, *b2b, *b3b;
    cudaGetSymbolAddress((void**)&p,    g_p);
    cudaGetSymbolAddress((void**)&h,    g_h);
    cudaGetSymbolAddress((void**)&hb,   g_hb);
    cudaGetSymbolAddress((void**)&h2,   g_h2);
    cudaGetSymbolAddress((void**)&h2m,  g_h2m);
    cudaGetSymbolAddress((void**)&base, g_base);
    cudaGetSymbolAddress((void**)&coef, g_coef);
    cudaGetSymbolAddress((void**)&W1b,  g_W1b);
    cudaGetSymbolAddress((void**)&W2b,  g_W2b);
    cudaGetSymbolAddress((void**)&W3b,  g_W3b);
    cudaGetSymbolAddress((void**)&b1b,  g_b1b);
    cudaGetSymbolAddress((void**)&b2b,  g_b2b);
    cudaGetSymbolAddress((void**)&b3b,  g_b3b);

    // 1) patchify
    {
        long n = (long)BP * Dd;
        patchify_kernel<<<(unsigned)((n + 255) / 256), 256>>>(x, p);
    }

    // 2) base layer1: h = relu(p @ W1 + b1)    [6272,768]
    gemm_kernel<<<dim3(BP / 64, Dd / 64, 1), 256>>>(
        p, 0, W1, 0, b1, 0, h, 0, BP, Dd, Dd, 1);

    // 3) base layer2: h2 = relu(h @ W2 + b2)   [6272,3072]
    gemm_kernel<<<dim3(BP / 64, DHh / 64, 1), 256>>>(
        h, 0, W2, 0, b2, 0, h2, 0, BP, DHh, Dd, 1);

    // 4) mean pool -> h2m [32,3072]
    mean_kernel<<<(Bn * DHh + 255) / 256, 256>>>(h2, h2m);

    // 5) base = h2m @ W3 + b3   [32,512]
    rowgemm_kernel<<<dim3(Bn, Ff / 128), 128>>>(h2m, W3, 0, b3, 0, base, Ff, DHh);

    // 6) MetaNet -> coefs [32,8]
    meta_kernel<<<Bn, MHh>>>(base, mW1, mb1, mW2, mb2, coef);

    // 7) compose per-sample parameters
    {
        long S1 = (long)Dd * Dd;   // 589824
        long S2 = (long)Dd * DHh;  // 2359296
        long S3 = (long)DHh * Ff;  // 1572864
        compose_kernel<<<(unsigned)((S1 + 255) / 256), 256>>>(W1, dW1, coef, W1b, S1);
        compose_kernel<<<(unsigned)((S2 + 255) / 256), 256>>>(W2, dW2, coef, W2b, S2);
        compose_kernel<<<(unsigned)((S3 + 255) / 256), 256>>>(W3, dW3, coef, W3b, S3);
        compose_kernel<<<(Dd  + 255) / 256, 256>>>(b1, db1, coef, b1b, Dd);
        compose_kernel<<<(DHh + 255) / 256, 256>>>(b2, db2, coef, b2b, DHh);
        compose_kernel<<<(Ff  + 255) / 256, 256>>>(b3, db3, coef, b3b, Ff);
    }

    // 8) adapted layer1: hb[b] = relu(p[b] @ W1b[b] + b1b[b])   batch=32, M=196
    gemm_kernel<<<dim3((Pp + 63) / 64, Dd / 64, Bn), 256>>>(
        p,  (long)Pp * Dd,
        W1b, (long)Dd * Dd,
        b1b, (long)Dd,
        hb, (long)Pp * Dd,
        Pp, Dd, Dd, 1);

    // 9) adapted layer2: h2[b] = relu(hb[b] @ W2b[b] + b2b[b])  batch=32
    gemm_kernel<<<dim3((Pp + 63) / 64, DHh / 64, Bn), 256>>>(
        hb,  (long)Pp * Dd,
        W2b, (long)Dd * DHh,
        b2b, (long)DHh,
        h2,  (long)Pp * DHh,
        Pp, DHh, Dd, 1);

    // 10) mean pool -> h2m [32,3072]
    mean_kernel<<<(Bn * DHh + 255) / 256, 256>>>(h2, h2m);

    // 11) out[b] = h2m[b] @ W3b[b] + b3b[b]    [32,512]
    rowgemm_kernel<<<dim3(Bn, Ff / 128), 128>>>(
        h2m, W3b, (long)DHh * Ff, b3b, (long)Ff, out, Ff, DHh);
}

// round 2
// speedup vs baseline: 1.6696x; 1.6696x over previous
#include <cuda_runtime.h>

// ---------------- problem constants ----------------
#define Bn   32
#define Tn   8
#define Dd   768
#define DHh  3072
#define Ff   512
#define MHh  128
#define Pp   196
#define BP   (Bn*Pp)

// ---------------- device scratch ----------------
__device__ float g_p   [(long)BP * Dd];
__device__ float g_h   [(long)BP * Dd];
__device__ float g_hb  [(long)BP * Dd];
__device__ float g_h2  [(long)BP * DHh];
__device__ float g_h2m [(long)Bn * DHh];
__device__ float g_base[(long)Bn * Ff];
__device__ float g_coef[(long)Bn * Tn];
__device__ float g_W1b [(long)Bn * Dd * Dd];
__device__ float g_W2b [(long)Bn * Dd * DHh];
__device__ float g_W3b [(long)Bn * DHh * Ff];
__device__ float g_b1b [(long)Bn * Dd];
__device__ float g_b2b [(long)Bn * DHh];
__device__ float g_b3b [(long)Bn * Ff];

// ---------------- patchify ----------------
__global__ void patchify_kernel(const float* __restrict__ x, float* __restrict__ p) {
    long idx = (long)blockIdx.x * blockDim.x + threadIdx.x;
    if (idx >= (long)BP * Dd) return;
    int d     = (int)(idx % Dd);
    long rem  = idx / Dd;
    int patch = (int)(rem % Pp);
    int b     = (int)(rem / Pp);
    int pi = patch / 14, pj = patch % 14;
    int c = d >> 8;
    int r = (d >> 4) & 15;
    int s = d & 15;
    p[idx] = x[((long)(b * 3 + c) * 224 + pi * 16 + r) * 224 + pj * 16 + s];
}

// ---------------- tf32 helpers ----------------
__device__ __forceinline__ float2 tf32_split(float x) {
    unsigned hi, lo;
    asm("cvt.rna.tf32.f32 %0, %1;" : "=r"(hi) : "f"(x));
    float hif = __uint_as_float(hi);
    asm("cvt.rna.tf32.f32 %0, %1;" : "=r"(lo) : "f"(x - hif));
    return make_float2(hif, __uint_as_float(lo));
}

__device__ __forceinline__ void mma_tf32(float* c, const unsigned* a, const unsigned* b) {
    asm volatile(
        "mma.sync.aligned.m16n8k8.row.col.f32.tf32.tf32.f32 "
        "{%0,%1,%2,%3}, {%4,%5,%6,%7}, {%8,%9}, {%0,%1,%2,%3};"
        : "+f"(c[0]), "+f"(c[1]), "+f"(c[2]), "+f"(c[3])
        : "r"(a[0]), "r"(a[1]), "r"(a[2]), "r"(a[3]), "r"(b[0]), "r"(b[1]));
}

// ---------------- tensor-core batched GEMM (3xTF32) ----------------
// C[b] = act(A[b](MxK,row) @ W[b](KxN,row) + bias[b]); K%16==0, N%64==0.
#define BM 128
#define BN 64
#define BK 16
#define KPAD 19
#define GEMM_SMEM ((2*BM*KPAD + 2*BN*KPAD) * (int)sizeof(float2))

__global__ void __launch_bounds__(256, 2) mma_gemm_kernel(
    const float* __restrict__ A, long aStride,
    const float* __restrict__ W, long wStride,
    const float* __restrict__ bias, long biasStride,
    float* __restrict__ C, long cStride,
    int M, int N, int K, int doRelu)
{
    int bz = blockIdx.z;
    A    += (long)bz * aStride;
    W    += (long)bz * wStride;
    bias += (long)bz * biasStride;
    C    += (long)bz * cStride;

    extern __shared__ float2 smem2[];
    float2 (*As)[BM][KPAD] = reinterpret_cast<float2(*)[BM][KPAD]>(smem2);
    float2 (*Bs)[BN][KPAD] = reinterpret_cast<float2(*)[BN][KPAD]>(smem2 + 2*BM*KPAD);

    int m0 = blockIdx.x * BM;
    int n0 = blockIdx.y * BN;
    int tid  = threadIdx.x;
    int lane = tid & 31;
    int warp = tid >> 5;
    int wm = warp & 3;        // 4 m-warps
    int wn = warp >> 2;       // 2 n-warps
    int g  = lane >> 2;       // groupID 0..7
    int c4 = lane & 3;        // 0..3

    // register staging for global loads
    float4 aReg[2];
    float4 bReg;

    int ntile = K / BK;

    // --- tile loaders ---
    auto loadTile = [&](int t) {
        int k0 = t * BK;
        #pragma unroll
        for (int i = 0; i < 2; i++) {
            int idx = tid + i * 256;
            int row = idx >> 2, kq = idx & 3;
            int gm = m0 + row;
            if (gm < M) aReg[i] = *(const float4*)(A + (long)gm * K + k0 + kq * 4);
            else        aReg[i] = make_float4(0.f, 0.f, 0.f, 0.f);
        }
        {
            int krow = tid >> 4, nq = tid & 15;
            bReg = *(const float4*)(W + (long)(k0 + krow) * N + n0 + nq * 4);
        }
    };
    auto storeTile = [&](int buf) {
        #pragma unroll
        for (int i = 0; i < 2; i++) {
            int idx = tid + i * 256;
            int row = idx >> 2, kq = idx & 3;
            As[buf][row][kq*4+0] = tf32_split(aReg[i].x);
            As[buf][row][kq*4+1] = tf32_split(aReg[i].y);
            As[buf][row][kq*4+2] = tf32_split(aReg[i].z);
            As[buf][row][kq*4+3] = tf32_split(aReg[i].w);
        }
        {
            int krow = tid >> 4, nq = tid & 15;
            Bs[buf][nq*4+0][krow] = tf32_split(bReg.x);
            Bs[buf][nq*4+1][krow] = tf32_split(bReg.y);
            Bs[buf][nq*4+2][krow] = tf32_split(bReg.z);
            Bs[buf][nq*4+3][krow] = tf32_split(bReg.w);
        }
    };

    float acc[2][4][4];
    #pragma unroll
    for (int i = 0; i < 2; i++)
        #pragma unroll
        for (int j = 0; j < 4; j++)
            #pragma unroll
            for (int k = 0; k < 4; k++) acc[i][j][k] = 0.f;

    // --- prologue ---
    loadTile(0);
    storeTile(0);
    if (ntile > 1) loadTile(1);
    __syncthreads();

    // --- main loop ---
    for (int t = 0; t < ntile; t++) {
        int cur = t & 1;
        if (t + 1 < ntile) {
            storeTile((t + 1) & 1);
            if (t + 2 < ntile) loadTile(t + 2);
        }
        const float2 (*Acur)[KPAD] = As[cur];
        const float2 (*Bcur)[KPAD] = Bs[cur];

        #pragma unroll
        for (int kk = 0; kk < BK; kk += 8) {
            unsigned ah[2][4], al[2][4];
            #pragma unroll
            for (int mt = 0; mt < 2; mt++) {
                int r = wm * 32 + mt * 16 + g;
                float2 v0 = Acur[r    ][kk + c4    ];
                float2 v1 = Acur[r + 8][kk + c4    ];
                float2 v2 = Acur[r    ][kk + c4 + 4];
                float2 v3 = Acur[r + 8][kk + c4 + 4];
                ah[mt][0] = __float_as_uint(v0.x); al[mt][0] = __float_as_uint(v0.y);
                ah[mt][1] = __float_as_uint(v1.x); al[mt][1] = __float_as_uint(v1.y);
                ah[mt][2] = __float_as_uint(v2.x); al[mt][2] = __float_as_uint(v2.y);
                ah[mt][3] = __float_as_uint(v3.x); al[mt][3] = __float_as_uint(v3.y);
            }
            unsigned bh[4][2], bl[4][2];
            #pragma unroll
            for (int nt = 0; nt < 4; nt++) {
                int n = wn * 32 + nt * 8 + g;
                float2 w0 = Bcur[n][kk + c4    ];
                float2 w1 = Bcur[n][kk + c4 + 4];
                bh[nt][0] = __float_as_uint(w0.x); bl[nt][0] = __float_as_uint(w0.y);
                bh[nt][1] = __float_as_uint(w1.x); bl[nt][1] = __float_as_uint(w1.y);
            }
            #pragma unroll
            for (int mt = 0; mt < 2; mt++)
                #pragma unroll
                for (int nt = 0; nt < 4; nt++) {
                    mma_tf32(acc[mt][nt], ah[mt], bh[nt]);   // hi*hi
                    mma_tf32(acc[mt][nt], al[mt], bh[nt]);   // lo*hi
                    mma_tf32(acc[mt][nt], ah[mt], bl[nt]);   // hi*lo
                }
        }
        __syncthreads();
    }

    // --- epilogue: bias + relu, float2 stores ---
    #pragma unroll
    for (int mt = 0; mt < 2; mt++) {
        int r0 = m0 + wm * 32 + mt * 16 + g;
        #pragma unroll
        for (int nt = 0; nt < 4; nt++) {
            int col = n0 + wn * 32 + nt * 8 + 2 * c4;
            float bx = bias[col], by = bias[col + 1];
            if (r0 < M) {
                float2 o = make_float2(acc[mt][nt][0] + bx, acc[mt][nt][1] + by);
                if (doRelu) { o.x = fmaxf(o.x, 0.f); o.y = fmaxf(o.y, 0.f); }
                *(float2*)(C + (long)r0 * N + col) = o;
            }
            if (r0 + 8 < M) {
                float2 o = make_float2(acc[mt][nt][2] + bx, acc[mt][nt][3] + by);
                if (doRelu) { o.x = fmaxf(o.x, 0.f); o.y = fmaxf(o.y, 0.f); }
                *(float2*)(C + (long)(r0 + 8) * N + col) = o;
            }
        }
    }
}

// ---------------- mean over the 196 patch rows ----------------
__global__ void mean_kernel(const float* __restrict__ H2, float* __restrict__ out) {
    int idx = blockIdx.x * blockDim.x + threadIdx.x;
    if (idx >= Bn * DHh) return;
    int b = idx / DHh, f = idx % DHh;
    const float* col = H2 + (long)b * Pp * DHh + f;
    float s = 0.f;
    for (int i = 0; i < Pp; i++) s += col[(long)i * DHh];
    out[idx] = s * (1.f / (float)Pp);
}

// ---------------- small-M GEMM with in-block split-K ----------------
// grid (Bn, N/32), block 256 = 32 n-lanes x 8 k-groups. K%8==0.
__global__ void rowgemm_kernel(const float* __restrict__ A,
                               const float* __restrict__ W, long wStride,
                               const float* __restrict__ bias, long biasStride,
                               float* __restrict__ C, int N, int K)
{
    int b  = blockIdx.x;
    int nl = threadIdx.x & 31;
    int kg = threadIdx.x >> 5;
    int n  = blockIdx.y * 32 + nl;
    const float* a = A + (long)b * K;
    const float* w = W + (long)b * wStride;
    int kchunk = K / 8;
    float acc = 0.f;
    for (int k = kg * kchunk; k < (kg + 1) * kchunk; k++)
        acc = fmaf(a[k], w[(long)k * N + n], acc);
    __shared__ float red[8][32];
    red[kg][nl] = acc;
    __syncthreads();
    if (kg == 0) {
        float s = acc;
        #pragma unroll
        for (int j = 1; j < 8; j++) s += red[j][nl];
        C[(long)b * N + n] = s + bias[(long)b * biasStride + n];
    }
}

// ---------------- MetaNet ----------------
__global__ void meta_kernel(const float* __restrict__ base,
                            const float* __restrict__ mW1, const float* __restrict__ mb1,
                            const float* __restrict__ mW2, const float* __restrict__ mb2,
                            float* __restrict__ coef)
{
    int b = blockIdx.x;
    __shared__ float br[Ff];
    __shared__ float hid[MHh];
    int t = threadIdx.x;
    for (int i = t; i < Ff; i += MHh) br[i] = base[b * Ff + i];
    __syncthreads();
    float acc = mb1[t];
    for (int e = 0; e < Ff; e++) acc = fmaf(br[e], mW1[e * MHh + t], acc);
    hid[t] = fmaxf(acc, 0.f);
    __syncthreads();
    if (t < Tn) {
        float c = mb2[t];
        for (int j = 0; j < MHh; j++) c = fmaf(hid[j], mW2[j * Tn + t], c);
        coef[b * Tn + t] = c;
    }
}

// ---------------- compose ----------------
__global__ void compose_kernel(const float* __restrict__ W, const float* __restrict__ dW,
                               const float* __restrict__ coef, float* __restrict__ out, long S)
{
    __shared__ float cs[Bn * Tn];
    if (threadIdx.x < Bn * Tn) cs[threadIdx.x] = coef[threadIdx.x];
    __syncthreads();
    long i = (long)blockIdx.x * blockDim.x + threadIdx.x;
    if (i >= S) return;
    float w = W[i];
    float d[Tn];
    #pragma unroll
    for (int t = 0; t < Tn; t++) d[t] = dW[(long)t * S + i];
    #pragma unroll 4
    for (int b = 0; b < Bn; b++) {
        float v = w;
        #pragma unroll
        for (int t = 0; t < Tn; t++) v = fmaf(cs[b * Tn + t], d[t], v);
        out[(long)b * S + i] = v;
    }
}

// ---------------- launch ----------------
extern "C" void kernel_launch(void* const* d_in, const int* in_sizes, int n_in,
                              void* d_out, int out_size)
{
    const float* x   = (const float*)d_in[0];
    const float* W1  = (const float*)d_in[1];
    const float* b1  = (const float*)d_in[2];
    const float* W2  = (const float*)d_in[3];
    const float* b2  = (const float*)d_in[4];
    const float* W3  = (const float*)d_in[5];
    const float* b3  = (const float*)d_in[6];
    const float* dW1 = (const float*)d_in[7];
    const float* db1 = (const float*)d_in[8];
    const float* dW2 = (const float*)d_in[9];
    const float* db2 = (const float*)d_in[10];
    const float* dW3 = (const float*)d_in[11];
    const float* db3 = (const float*)d_in[12];
    const float* mW1 = (const float*)d_in[13];
    const float* mb1 = (const float*)d_in[14];
    const float* mW2 = (const float*)d_in[15];
    const float* mb2 = (const float*)d_in[16];
    float* out = (float*)d_out;

    float *p, *h, *hb, *h2, *h2m, *base, *coef;
    float *W1b, *W2b, *W3b, *b1b, *b2b, *b3b;
    cudaGetSymbolAddress((void**)&p,    g_p);
    cudaGetSymbolAddress((void**)&h,    g_h);
    cudaGetSymbolAddress((void**)&hb,   g_hb);
    cudaGetSymbolAddress((void**)&h2,   g_h2);
    cudaGetSymbolAddress((void**)&h2m,  g_h2m);
    cudaGetSymbolAddress((void**)&base, g_base);
    cudaGetSymbolAddress((void**)&coef, g_coef);
    cudaGetSymbolAddress((void**)&W1b,  g_W1b);
    cudaGetSymbolAddress((void**)&W2b,  g_W2b);
    cudaGetSymbolAddress((void**)&W3b,  g_W3b);
    cudaGetSymbolAddress((void**)&b1b,  g_b1b);
    cudaGetSymbolAddress((void**)&b2b,  g_b2b);
    cudaGetSymbolAddress((void**)&b3b,  g_b3b);

    cudaFuncSetAttribute(mma_gemm_kernel,
                         cudaFuncAttributeMaxDynamicSharedMemorySize, GEMM_SMEM);

    // 1) patchify
    {
        long n = (long)BP * Dd;
        patchify_kernel<<<(unsigned)((n + 255) / 256), 256>>>(x, p);
    }

    // 2) base layer1: h = relu(p @ W1 + b1)
    mma_gemm_kernel<<<dim3((BP + BM - 1) / BM, Dd / BN, 1), 256, GEMM_SMEM>>>(
        p, 0, W1, 0, b1, 0, h, 0, BP, Dd, Dd, 1);

    // 3) base layer2: h2 = relu(h @ W2 + b2)
    mma_gemm_kernel<<<dim3((BP + BM - 1) / BM, DHh / BN, 1), 256, GEMM_SMEM>>>(
        h, 0, W2, 0, b2, 0, h2, 0, BP, DHh, Dd, 1);

    // 4) mean pool
    mean_kernel<<<(Bn * DHh + 255) / 256, 256>>>(h2, h2m);

    // 5) base = h2m @ W3 + b3
    rowgemm_kernel<<<dim3(Bn, Ff / 32), 256>>>(h2m, W3, 0, b3, 0, base, Ff, DHh);

    // 6) MetaNet -> coefs
    meta_kernel<<<Bn, MHh>>>(base, mW1, mb1, mW2, mb2, coef);

    // 7) compose per-sample parameters
    {
        long S1 = (long)Dd * Dd;
        long S2 = (long)Dd * DHh;
        long S3 = (long)DHh * Ff;
        compose_kernel<<<(unsigned)((S1 + 255) / 256), 256>>>(W1, dW1, coef, W1b, S1);
        compose_kernel<<<(unsigned)((S2 + 255) / 256), 256>>>(W2, dW2, coef, W2b, S2);
        compose_kernel<<<(unsigned)((S3 + 255) / 256), 256>>>(W3, dW3, coef, W3b, S3);
        compose_kernel<<<(Dd  + 255) / 256, 256>>>(b1, db1, coef, b1b, Dd);
        compose_kernel<<<(DHh + 255) / 256, 256>>>(b2, db2, coef, b2b, DHh);
        compose_kernel<<<(Ff  + 255) / 256, 256>>>(b3, db3, coef, b3b, Ff);
    }

    // 8) adapted layer1 (batched over 32 samples)
    mma_gemm_kernel<<<dim3((Pp + BM - 1) / BM, Dd / BN, Bn), 256, GEMM_SMEM>>>(
        p,   (long)Pp * Dd,
        W1b, (long)Dd * Dd,
        b1b, (long)Dd,
        hb,  (long)Pp * Dd,
        Pp, Dd, Dd, 1);

    // 9) adapted layer2
    mma_gemm_kernel<<<dim3((Pp + BM - 1) / BM, DHh / BN, Bn), 256, GEMM_SMEM>>>(
        hb,  (long)Pp * Dd,
        W2b, (long)Dd * DHh,
        b2b, (long)DHh,
        h2,  (long)Pp * DHh,
        Pp, DHh, Dd, 1);

    // 10) mean pool
    mean_kernel<<<(Bn * DHh + 255) / 256, 256>>>(h2, h2m);

    // 11) out = h2m @ W3b + b3b
    rowgemm_kernel<<<dim3(Bn, Ff / 32), 256>>>(
        h2m, W3b, (long)DHh * Ff, b3b, (long)Ff, out, Ff, DHh);
}

// round 3
// speedup vs baseline: 3.5914x; 2.1511x over previous
#include <cuda_runtime.h>
#include <cuda_bf16.h>

// ---------------- problem constants ----------------
#define Bn   32
#define Tn   8
#define Dd   768
#define DHh  3072
#define Ff   512
#define MHh  128
#define Pp   196
#define BP   (Bn*Pp)

// ---------------- device scratch ----------------
__device__ float g_p   [(long)BP * Dd];
__device__ float g_h   [(long)BP * Dd];
__device__ float g_hb  [(long)BP * Dd];
__device__ float g_h2  [(long)BP * DHh];
__device__ float g_h2m [(long)Bn * DHh];
__device__ float g_base[(long)Bn * Ff];
__device__ float g_coef[(long)Bn * Tn];
__device__ float g_W1b [(long)Bn * Dd * Dd];
__device__ float g_W2b [(long)Bn * Dd * DHh];
__device__ float g_W3b [(long)Bn * DHh * Ff];
__device__ float g_b1b [(long)Bn * Dd];
__device__ float g_b2b [(long)Bn * DHh];
__device__ float g_b3b [(long)Bn * Ff];

// ---------------- patchify ----------------
__global__ void patchify_kernel(const float* __restrict__ x, float* __restrict__ p) {
    long idx = (long)blockIdx.x * blockDim.x + threadIdx.x;
    if (idx >= (long)BP * Dd) return;
    int d     = (int)(idx % Dd);
    long rem  = idx / Dd;
    int patch = (int)(rem % Pp);
    int b     = (int)(rem / Pp);
    int pi = patch / 14, pj = patch % 14;
    int c = d >> 8;
    int r = (d >> 4) & 15;
    int s = d & 15;
    p[idx] = x[((long)(b * 3 + c) * 224 + pi * 16 + r) * 224 + pj * 16 + s];
}

// ---------------- bf16 split helpers ----------------
__device__ __forceinline__ void split2(float x, float y, unsigned& hi, unsigned& lo) {
    __nv_bfloat16 hx = __float2bfloat16(x);
    __nv_bfloat16 hy = __float2bfloat16(y);
    __nv_bfloat16 lx = __float2bfloat16(x - __bfloat162float(hx));
    __nv_bfloat16 ly = __float2bfloat16(y - __bfloat162float(hy));
    __nv_bfloat162 h2v(hx, hy), l2v(lx, ly);
    hi = *reinterpret_cast<unsigned*>(&h2v);
    lo = *reinterpret_cast<unsigned*>(&l2v);
}

__device__ __forceinline__ void mma_bf16(float* c, const unsigned* a, const unsigned* b) {
    asm volatile(
        "mma.sync.aligned.m16n8k16.row.col.f32.bf16.bf16.f32 "
        "{%0,%1,%2,%3}, {%4,%5,%6,%7}, {%8,%9}, {%0,%1,%2,%3};"
        : "+f"(c[0]), "+f"(c[1]), "+f"(c[2]), "+f"(c[3])
        : "r"(a[0]), "r"(a[1]), "r"(a[2]), "r"(a[3]), "r"(b[0]), "r"(b[1]));
}

__device__ __forceinline__ void ldsm_x4(unsigned* r, unsigned addr) {
    asm volatile("ldmatrix.sync.aligned.m8n8.x4.shared.b16 {%0,%1,%2,%3}, [%4];"
                 : "=r"(r[0]), "=r"(r[1]), "=r"(r[2]), "=r"(r[3]) : "r"(addr));
}
__device__ __forceinline__ void ldsm_x2t(unsigned* r, unsigned addr) {
    asm volatile("ldmatrix.sync.aligned.m8n8.x2.trans.shared.b16 {%0,%1}, [%2];"
                 : "=r"(r[0]), "=r"(r[1]) : "r"(addr));
}

// ---------------- tensor-core batched GEMM (bf16 2-way split, 3 passes) ----------------
// C[b] = act(A[b](MxK,row) @ W[b](KxN,row) + bias[b]); K%16==0, N%64==0.
#define BM 128
#define BN 64
#define BK 16
#define APITCH 24   // bf16 elems per A smem row (16 data + 8 pad) -> 48B
#define BPITCH 72   // bf16 elems per B smem row (64 data + 8 pad) -> 144B
#define A_PLANE (BM*APITCH)   // bf16 elems
#define B_PLANE (BK*BPITCH)

__global__ void __launch_bounds__(256, 2) mma_gemm_kernel(
    const float* __restrict__ A, long aStride,
    const float* __restrict__ W, long wStride,
    const float* __restrict__ bias, long biasStride,
    float* __restrict__ C, long cStride,
    int M, int N, int K, int doRelu)
{
    int bz = blockIdx.z;
    A    += (long)bz * aStride;
    W    += (long)bz * wStride;
    bias += (long)bz * biasStride;
    C    += (long)bz * cStride;

    // [buf][plane][...]
    __shared__ __nv_bfloat16 sA[2][2][A_PLANE];
    __shared__ __nv_bfloat16 sB[2][2][B_PLANE];

    int m0 = blockIdx.x * BM;
    int n0 = blockIdx.y * BN;
    int tid  = threadIdx.x;
    int lane = tid & 31;
    int warp = tid >> 5;
    int wm = warp & 3;        // 4 m-warps (32 rows each)
    int wn = warp >> 2;       // 2 n-warps (32 cols each)

    // ldmatrix lane addressing
    unsigned aBase = (unsigned)__cvta_generic_to_shared(&sA[0][0][0]);
    unsigned bBase = (unsigned)__cvta_generic_to_shared(&sB[0][0][0]);
    // A frag: row = wm*32 + mt*16 + (lane&15), col = (lane>>4)*8
    int aRowInWarp = (lane & 15);
    int aColOff    = (lane >> 4) * 8;
    unsigned aAddr[2]; // per mt, within buf0/plane0
    #pragma unroll
    for (int mt = 0; mt < 2; mt++)
        aAddr[mt] = aBase + (unsigned)(((wm * 32 + mt * 16 + aRowInWarp) * APITCH + aColOff) * 2);
    // B frag: k-row = (lane&15), col base = wn*32 + nt*8
    unsigned bAddr[4];
    #pragma unroll
    for (int nt = 0; nt < 4; nt++)
        bAddr[nt] = bBase + (unsigned)(((lane & 15) * BPITCH + wn * 32 + nt * 8) * 2);

    const unsigned A_PLANE_B = A_PLANE * 2;       // bytes
    const unsigned A_BUF_B   = 2 * A_PLANE_B;
    const unsigned B_PLANE_B = B_PLANE * 2;
    const unsigned B_BUF_B   = 2 * B_PLANE_B;

    // global-load staging registers
    float4 aReg[2];
    float4 bReg;

    int ntile = K / BK;

    auto loadTile = [&](int t) {
        int k0 = t * BK;
        #pragma unroll
        for (int i = 0; i < 2; i++) {
            int idx = tid + i * 256;
            int row = idx >> 2, kq = idx & 3;
            int gm = m0 + row;
            if (gm < M) aReg[i] = *(const float4*)(A + (long)gm * K + k0 + kq * 4);
            else        aReg[i] = make_float4(0.f, 0.f, 0.f, 0.f);
        }
        {
            int krow = tid >> 4, nq = tid & 15;
            bReg = *(const float4*)(W + (long)(k0 + krow) * N + n0 + nq * 4);
        }
    };
    auto storeTile = [&](int buf) {
        #pragma unroll
        for (int i = 0; i < 2; i++) {
            int idx = tid + i * 256;
            int row = idx >> 2, kq = idx & 3;
            unsigned h0, l0, h1, l1;
            split2(aReg[i].x, aReg[i].y, h0, l0);
            split2(aReg[i].z, aReg[i].w, h1, l1);
            int e = row * APITCH + kq * 4;
            *(uint2*)(&sA[buf][0][e]) = make_uint2(h0, h1);
            *(uint2*)(&sA[buf][1][e]) = make_uint2(l0, l1);
        }
        {
            int krow = tid >> 4, nq = tid & 15;
            unsigned h0, l0, h1, l1;
            split2(bReg.x, bReg.y, h0, l0);
            split2(bReg.z, bReg.w, h1, l1);
            int e = krow * BPITCH + nq * 4;
            *(uint2*)(&sB[buf][0][e]) = make_uint2(h0, h1);
            *(uint2*)(&sB[buf][1][e]) = make_uint2(l0, l1);
        }
    };

    float acc[2][4][4];
    #pragma unroll
    for (int i = 0; i < 2; i++)
        #pragma unroll
        for (int j = 0; j < 4; j++)
            #pragma unroll
            for (int k = 0; k < 4; k++) acc[i][j][k] = 0.f;

    // prologue
    loadTile(0);
    storeTile(0);
    if (ntile > 1) loadTile(1);
    __syncthreads();

    for (int t = 0; t < ntile; t++) {
        int cur = t & 1;
        if (t + 1 < ntile) {
            storeTile((t + 1) & 1);
            if (t + 2 < ntile) loadTile(t + 2);
        }
        unsigned aOff = (unsigned)cur * A_BUF_B;
        unsigned bOff = (unsigned)cur * B_BUF_B;

        unsigned afr[2][2][4]; // [plane][mt][4]
        #pragma unroll
        for (int mt = 0; mt < 2; mt++) {
            ldsm_x4(afr[0][mt], aAddr[mt] + aOff);
            ldsm_x4(afr[1][mt], aAddr[mt] + aOff + A_PLANE_B);
        }
        unsigned bfr[2][4][2]; // [plane][nt][2]
        #pragma unroll
        for (int nt = 0; nt < 4; nt++) {
            ldsm_x2t(bfr[0][nt], bAddr[nt] + bOff);
            ldsm_x2t(bfr[1][nt], bAddr[nt] + bOff + B_PLANE_B);
        }
        #pragma unroll
        for (int mt = 0; mt < 2; mt++)
            #pragma unroll
            for (int nt = 0; nt < 4; nt++) {
                mma_bf16(acc[mt][nt], afr[0][mt], bfr[0][nt]);  // hi*hi
                mma_bf16(acc[mt][nt], afr[1][mt], bfr[0][nt]);  // lo*hi
                mma_bf16(acc[mt][nt], afr[0][mt], bfr[1][nt]);  // hi*lo
            }
        __syncthreads();
    }

    // epilogue: bias + relu, float2 stores
    int g  = lane >> 2;
    int c4 = lane & 3;
    #pragma unroll
    for (int mt = 0; mt < 2; mt++) {
        int r0 = m0 + wm * 32 + mt * 16 + g;
        #pragma unroll
        for (int nt = 0; nt < 4; nt++) {
            int col = n0 + wn * 32 + nt * 8 + 2 * c4;
            float bx = bias[col], by = bias[col + 1];
            if (r0 < M) {
                float2 o = make_float2(acc[mt][nt][0] + bx, acc[mt][nt][1] + by);
                if (doRelu) { o.x = fmaxf(o.x, 0.f); o.y = fmaxf(o.y, 0.f); }
                *(float2*)(C + (long)r0 * N + col) = o;
            }
            if (r0 + 8 < M) {
                float2 o = make_float2(acc[mt][nt][2] + bx, acc[mt][nt][3] + by);
                if (doRelu) { o.x = fmaxf(o.x, 0.f); o.y = fmaxf(o.y, 0.f); }
                *(float2*)(C + (long)(r0 + 8) * N + col) = o;
            }
        }
    }
}

// ---------------- mean over the 196 patch rows ----------------
__global__ void mean_kernel(const float* __restrict__ H2, float* __restrict__ out) {
    int idx = blockIdx.x * blockDim.x + threadIdx.x;
    if (idx >= Bn * DHh) return;
    int b = idx / DHh, f = idx % DHh;
    const float* col = H2 + (long)b * Pp * DHh + f;
    float s = 0.f;
    for (int i = 0; i < Pp; i++) s += col[(long)i * DHh];
    out[idx] = s * (1.f / (float)Pp);
}

// ---------------- small-M GEMM with in-block split-K ----------------
__global__ void rowgemm_kernel(const float* __restrict__ A,
                               const float* __restrict__ W, long wStride,
                               const float* __restrict__ bias, long biasStride,
                               float* __restrict__ C, int N, int K)
{
    int b  = blockIdx.x;
    int nl = threadIdx.x & 31;
    int kg = threadIdx.x >> 5;
    int n  = blockIdx.y * 32 + nl;
    const float* a = A + (long)b * K;
    const float* w = W + (long)b * wStride;
    int kchunk = K / 8;
    float acc = 0.f;
    for (int k = kg * kchunk; k < (kg + 1) * kchunk; k++)
        acc = fmaf(a[k], w[(long)k * N + n], acc);
    __shared__ float red[8][32];
    red[kg][nl] = acc;
    __syncthreads();
    if (kg == 0) {
        float s = acc;
        #pragma unroll
        for (int j = 1; j < 8; j++) s += red[j][nl];
        C[(long)b * N + n] = s + bias[(long)b * biasStride + n];
    }
}

// ---------------- MetaNet ----------------
__global__ void meta_kernel(const float* __restrict__ base,
                            const float* __restrict__ mW1, const float* __restrict__ mb1,
                            const float* __restrict__ mW2, const float* __restrict__ mb2,
                            float* __restrict__ coef)
{
    int b = blockIdx.x;
    __shared__ float br[Ff];
    __shared__ float hid[MHh];
    int t = threadIdx.x;
    for (int i = t; i < Ff; i += MHh) br[i] = base[b * Ff + i];
    __syncthreads();
    float acc = mb1[t];
    for (int e = 0; e < Ff; e++) acc = fmaf(br[e], mW1[e * MHh + t], acc);
    hid[t] = fmaxf(acc, 0.f);
    __syncthreads();
    if (t < Tn) {
        float c = mb2[t];
        for (int j = 0; j < MHh; j++) c = fmaf(hid[j], mW2[j * Tn + t], c);
        coef[b * Tn + t] = c;
    }
}

// ---------------- compose ----------------
__global__ void compose_kernel(const float* __restrict__ W, const float* __restrict__ dW,
                               const float* __restrict__ coef, float* __restrict__ out, long S)
{
    __shared__ float cs[Bn * Tn];
    if (threadIdx.x < Bn * Tn) cs[threadIdx.x] = coef[threadIdx.x];
    __syncthreads();
    long i = (long)blockIdx.x * blockDim.x + threadIdx.x;
    if (i >= S) return;
    float w = W[i];
    float d[Tn];
    #pragma unroll
    for (int t = 0; t < Tn; t++) d[t] = dW[(long)t * S + i];
    #pragma unroll 4
    for (int b = 0; b < Bn; b++) {
        float v = w;
        #pragma unroll
        for (int t = 0; t < Tn; t++) v = fmaf(cs[b * Tn + t], d[t], v);
        out[(long)b * S + i] = v;
    }
}

// ---------------- launch ----------------
extern "C" void kernel_launch(void* const* d_in, const int* in_sizes, int n_in,
                              void* d_out, int out_size)
{
    const float* x   = (const float*)d_in[0];
    const float* W1  = (const float*)d_in[1];
    const float* b1  = (const float*)d_in[2];
    const float* W2  = (const float*)d_in[3];
    const float* b2  = (const float*)d_in[4];
    const float* W3  = (const float*)d_in[5];
    const float* b3  = (const float*)d_in[6];
    const float* dW1 = (const float*)d_in[7];
    const float* db1 = (const float*)d_in[8];
    const float* dW2 = (const float*)d_in[9];
    const float* db2 = (const float*)d_in[10];
    const float* dW3 = (const float*)d_in[11];
    const float* db3 = (const float*)d_in[12];
    const float* mW1 = (const float*)d_in[13];
    const float* mb1 = (const float*)d_in[14];
    const float* mW2 = (const float*)d_in[15];
    const float* mb2 = (const float*)d_in[16];
    float* out = (float*)d_out;

    float *p, *h, *hb, *h2, *h2m, *base, *coef;
    float *W1b, *W2b, *W3b, *b1b, *b2b, *b3b;
    cudaGetSymbolAddress((void**)&p,    g_p);
    cudaGetSymbolAddress((void**)&h,    g_h);
    cudaGetSymbolAddress((void**)&hb,   g_hb);
    cudaGetSymbolAddress((void**)&h2,   g_h2);
    cudaGetSymbolAddress((void**)&h2m,  g_h2m);
    cudaGetSymbolAddress((void**)&base, g_base);
    cudaGetSymbolAddress((void**)&coef, g_coef);
    cudaGetSymbolAddress((void**)&W1b,  g_W1b);
    cudaGetSymbolAddress((void**)&W2b,  g_W2b);
    cudaGetSymbolAddress((void**)&W3b,  g_W3b);
    cudaGetSymbolAddress((void**)&b1b,  g_b1b);
    cudaGetSymbolAddress((void**)&b2b,  g_b2b);
    cudaGetSymbolAddress((void**)&b3b,  g_b3b);

    // 1) patchify
    {
        long n = (long)BP * Dd;
        patchify_kernel<<<(unsigned)((n + 255) / 256), 256>>>(x, p);
    }

    // 2) base layer1: h = relu(p @ W1 + b1)
    mma_gemm_kernel<<<dim3(BP / BM, Dd / BN, 1), 256>>>(
        p, 0, W1, 0, b1, 0, h, 0, BP, Dd, Dd, 1);

    // 3) base layer2: h2 = relu(h @ W2 + b2)
    mma_gemm_kernel<<<dim3(BP / BM, DHh / BN, 1), 256>>>(
        h, 0, W2, 0, b2, 0, h2, 0, BP, DHh, Dd, 1);

    // 4) mean pool
    mean_kernel<<<(Bn * DHh + 255) / 256, 256>>>(h2, h2m);

    // 5) base = h2m @ W3 + b3
    rowgemm_kernel<<<dim3(Bn, Ff / 32), 256>>>(h2m, W3, 0, b3, 0, base, Ff, DHh);

    // 6) MetaNet -> coefs
    meta_kernel<<<Bn, MHh>>>(base, mW1, mb1, mW2, mb2, coef);

    // 7) compose per-sample parameters
    {
        long S1 = (long)Dd * Dd;
        long S2 = (long)Dd * DHh;
        long S3 = (long)DHh * Ff;
        compose_kernel<<<(unsigned)((S1 + 255) / 256), 256>>>(W1, dW1, coef, W1b, S1);
        compose_kernel<<<(unsigned)((S2 + 255) / 256), 256>>>(W2, dW2, coef, W2b, S2);
        compose_kernel<<<(unsigned)((S3 + 255) / 256), 256>>>(W3, dW3, coef, W3b, S3);
        compose_kernel<<<(Dd  + 255) / 256, 256>>>(b1, db1, coef, b1b, Dd);
        compose_kernel<<<(DHh + 255) / 256, 256>>>(b2, db2, coef, b2b, DHh);
        compose_kernel<<<(Ff  + 255) / 256, 256>>>(b3, db3, coef, b3b, Ff);
    }

    // 8) adapted layer1 (batched over 32 samples)
    mma_gemm_kernel<<<dim3((Pp + BM - 1) / BM, Dd / BN, Bn), 256>>>(
        p,   (long)Pp * Dd,
        W1b, (long)Dd * Dd,
        b1b, (long)Dd,
        hb,  (long)Pp * Dd,
        Pp, Dd, Dd, 1);

    // 9) adapted layer2
    mma_gemm_kernel<<<dim3((Pp + BM - 1) / BM, DHh / BN, Bn), 256>>>(
        hb,  (long)Pp * Dd,
        W2b, (long)Dd * DHh,
        b2b, (long)DHh,
        h2,  (long)Pp * DHh,
        Pp, DHh, Dd, 1);

    // 10) mean pool
    mean_kernel<<<(Bn * DHh + 255) / 256, 256>>>(h2, h2m);

    // 11) out = h2m @ W3b + b3b
    rowgemm_kernel<<<dim3(Bn, Ff / 32), 256>>>(
        h2m, W3b, (long)DHh * Ff, b3b, (long)Ff, out, Ff, DHh);
}